// round 6
// baseline (speedup 1.0000x reference)
#include <cuda_runtime.h>

#define THREADS 128
#define RPC 8          // rows per CTA
#define WS 128         // Wt row stride (floats)
#define XS 128         // xs row stride (floats) — rotated layout, no pad needed
#define QS 132         // qk row stride (floats), mult of 4, not mult of 32

// shared memory layout (float offsets)
#define OFF_W   0
#define OFF_X   (128*WS)            // 16384
#define OFF_QK  (OFF_X + 32*XS)     // +4096
#define OFF_B   (OFF_QK + 32*QS)    // +4224
#define OFF_WR  (OFF_B + 128)
#define OFF_CWS (OFF_WR + 32)
#define OFF_CS  (OFF_CWS + 128)
#define SMEM_FLOATS (OFF_CS + 32)   // 25024 floats = 100096 B -> 2 CTAs/SM

// ---- packed fp32x2 helpers (sm_10x FFMA2 path, PTX-only) ----
__device__ __forceinline__ unsigned long long ffma2(unsigned long long a,
                                                    unsigned long long b,
                                                    unsigned long long c) {
    unsigned long long d;
    asm("fma.rn.f32x2 %0, %1, %2, %3;" : "=l"(d) : "l"(a), "l"(b), "l"(c));
    return d;
}
__device__ __forceinline__ unsigned long long dup2(float x) {
    unsigned long long r;
    asm("mov.b64 %0, {%1, %1};" : "=l"(r) : "f"(x));
    return r;
}
__device__ __forceinline__ void unpack2(unsigned long long v, float& lo, float& hi) {
    asm("mov.b64 {%0, %1}, %2;" : "=f"(lo), "=f"(hi) : "l"(v));
}

__global__ __launch_bounds__(THREADS, 2)
void concept_emb_kernel(const int*   __restrict__ g_ids,
                        const float* __restrict__ g_mask,
                        const float* __restrict__ g_times,
                        const float* __restrict__ g_emb,
                        const float* __restrict__ g_qW,
                        const float* __restrict__ g_qb,
                        const float* __restrict__ g_kW,
                        const float* __restrict__ g_kb,
                        const float* __restrict__ g_theta,
                        const float* __restrict__ g_mu,
                        float*       __restrict__ g_out,
                        int n_rows)
{
    extern __shared__ float sm[];
    float* Wt   = sm + OFF_W;    // [128 d][128] : Wt[d][j], j<64 = qW row j, j>=64 = kW row j-64
    float* xs   = sm + OFF_X;    // [32 n][128], ROTATED: x[n][d] at n*128 + ((d + (n&~3)) & 127)
    float* qk   = sm + OFF_QK;   // [32 n][132] : cols 0..63 = q, 64..127 = k (plain layout)
    float* bs   = sm + OFF_B;    // [128] combined bias
    float* wrow = sm + OFF_WR;   // [32] sx * mask per concept
    float* cws  = sm + OFF_CWS;  // [4 warps][32]
    float* cs   = sm + OFF_CS;   // [32] attention column weights

    const int t    = threadIdx.x;
    const int lane = t & 31;
    const int wid  = t >> 5;

    // phase-2 mapping: warp owns j-quarter [32*wid, 32*wid+32), all 32 n.
    const int jg = lane & 3;            // j-tile of 8 within quarter
    const int ng = lane >> 2;           // n-tile of 4
    const int jb = 32 * wid + 8 * jg;
    const int xrot = 4 * ng;            // rotation for rows 4ng..4ng+3

    // ---- stage [qW;kW] transposed into smem (once per CTA) ----
    {
        const float4* q4 = (const float4*)g_qW;
        const float4* k4 = (const float4*)g_kW;
        #pragma unroll
        for (int it = 0; it < 32; ++it) {
            int f  = it * 128 + t;       // float4 index in combined 4096
            int fl = f & 2047;
            float4 v = (f < 2048) ? q4[fl] : k4[fl];
            int j  = (fl >> 5) + ((f < 2048) ? 0 : 64);
            int d0 = (fl & 31) * 4;
            Wt[(d0+0)*WS + j] = v.x;
            Wt[(d0+1)*WS + j] = v.y;
            Wt[(d0+2)*WS + j] = v.z;
            Wt[(d0+3)*WS + j] = v.w;
        }
        bs[t] = (t < 64) ? g_qb[t] : g_kb[t - 64];
    }
    __syncthreads();

    // bias for this thread's 8-column j-tile, in registers across all rows
    const float4 b0 = *(const float4*)&bs[jb];
    const float4 b1 = *(const float4*)&bs[jb + 4];

    const int row0 = blockIdx.x * RPC;
    for (int rr = 0; rr < RPC; ++rr) {
        const int row = row0 + rr;
        const bool active = (row < n_rows);

        // ---- gather x[32][128] (rotated store) + pooling weights ----
        if (active) {
            const float4* emb4 = (const float4*)g_emb;
            #pragma unroll
            for (int r8 = 0; r8 < 8; ++r8) {
                int n = wid * 8 + r8;
                int id = g_ids[row * 32 + n];           // warp-uniform broadcast LDG
                float4 v = emb4[(long)id * 32 + lane];
                int off = (4 * lane + (n & ~3)) & 127;  // rotated column
                *(float4*)&xs[n * XS + off] = v;
            }
            if (t < 32) {
                int id = g_ids[row * 32 + t];
                float mk = g_mask[row * 32 + t];
                float tm = g_times[row];
                float z  = g_theta[id] - g_mu[id] * tm;
                float sx = 1.0f / (1.0f + __expf(-z));
                wrow[t] = sx * mk;
            }
        }
        __syncthreads();

        // ---- phase 2: [q|k] = x @ [qW;kW]^T ----
        // 4n x 8j per-thread tile; warp covers 32n x 32j (its j-quarter).
        if (active) {
            unsigned long long acc2[4][4];
            #pragma unroll
            for (int i = 0; i < 4; ++i)
                #pragma unroll
                for (int u = 0; u < 4; ++u) acc2[i][u] = 0ULL;

            const float* xbase = &xs[(ng * 4) * XS];
            const float* wp = &Wt[jb];
            #pragma unroll 2
            for (int ds = 0; ds < 32; ++ds) {
                const int d = ds * 4;
                const int xoff = (d + xrot) & 127;      // same for all 4 rows
                float4 xv[4];
                #pragma unroll
                for (int i = 0; i < 4; ++i)
                    xv[i] = *(const float4*)(xbase + i * XS + xoff);
                #pragma unroll
                for (int e = 0; e < 4; ++e) {
                    const float* wr = wp + (d + e) * WS;
                    ulonglong2 wa = *(const ulonglong2*)(wr);       // j: jb..jb+3
                    ulonglong2 wb = *(const ulonglong2*)(wr + 4);   // j: jb+4..jb+7
                    #pragma unroll
                    for (int i = 0; i < 4; ++i) {
                        const float* xf = (const float*)&xv[i];
                        unsigned long long xd = dup2(xf[e]);
                        acc2[i][0] = ffma2(xd, wa.x, acc2[i][0]);
                        acc2[i][1] = ffma2(xd, wa.y, acc2[i][1]);
                        acc2[i][2] = ffma2(xd, wb.x, acc2[i][2]);
                        acc2[i][3] = ffma2(xd, wb.y, acc2[i][3]);
                    }
                }
            }
            #pragma unroll
            for (int i = 0; i < 4; ++i) {
                int n = ng * 4 + i;
                float v0,v1,v2,v3,v4,v5,v6,v7;
                unpack2(acc2[i][0], v0, v1);
                unpack2(acc2[i][1], v2, v3);
                unpack2(acc2[i][2], v4, v5);
                unpack2(acc2[i][3], v6, v7);
                float4 o0 = {v0 + b0.x, v1 + b0.y, v2 + b0.z, v3 + b0.w};
                float4 o1 = {v4 + b1.x, v5 + b1.y, v6 + b1.z, v7 + b1.w};
                *(float4*)&qk[n * QS + jb]     = o0;
                *(float4*)&qk[n * QS + jb + 4] = o1;
            }
        }
        __syncthreads();

        // ---- phase 3: scores (column m = lane), softmax via shuffles,
        //      fold pooling weights into column vector c; packed f32x2 dot ----
        if (active) {
            unsigned long long s2[8];
            #pragma unroll
            for (int i = 0; i < 8; ++i) s2[i] = 0ULL;
            const float* kp = &qk[lane * QS + 64];     // k row m = lane
            const float* qp = &qk[(wid * 8) * QS];     // q rows 8w..8w+7 (broadcast)
            #pragma unroll 2
            for (int hs = 0; hs < 16; ++hs) {
                const int h = hs * 4;
                ulonglong2 kv = *(const ulonglong2*)(kp + h);
                #pragma unroll
                for (int i = 0; i < 8; ++i) {
                    ulonglong2 qv = *(const ulonglong2*)(qp + i * QS + h);
                    s2[i] = ffma2(qv.x, kv.x, s2[i]);
                    s2[i] = ffma2(qv.y, kv.y, s2[i]);
                }
            }
            float cpart = 0.f;
            #pragma unroll
            for (int i = 0; i < 8; ++i) {
                float a, b;
                unpack2(s2[i], a, b);
                float v = (a + b) * 0.125f;            // / sqrt(H=64)
                float mx = v;
                #pragma unroll
                for (int o = 16; o > 0; o >>= 1)
                    mx = fmaxf(mx, __shfl_xor_sync(0xffffffffu, mx, o));
                float ex = __expf(v - mx);
                float sum = ex;
                #pragma unroll
                for (int o = 16; o > 0; o >>= 1)
                    sum += __shfl_xor_sync(0xffffffffu, sum, o);
                cpart = fmaf(__fdividef(wrow[wid * 8 + i], sum), ex, cpart);
            }
            cws[wid * 32 + lane] = cpart;
        }
        __syncthreads();

        if (active && t < 32)
            cs[t] = cws[t] + cws[32 + t] + cws[64 + t] + cws[96 + t];
        __syncthreads();

        // ---- phase 4: pooled[d] = sum_m c[m] * x[m][d] (rotated read) ----
        if (active) {
            float o = 0.f;
            #pragma unroll
            for (int m = 0; m < 32; ++m) {
                int off = (t + (m & ~3)) & 127;
                o = fmaf(cs[m], xs[m * XS + off], o);
            }
            g_out[(long)row * 128 + t] = o;
        }
        // protect xs/wrow against next iteration's gather writes
        __syncthreads();
    }
}

extern "C" void kernel_launch(void* const* d_in, const int* in_sizes, int n_in,
                              void* d_out, int out_size)
{
    (void)n_in; (void)out_size;
    const int*   g_ids   = (const int*)  d_in[0];
    const float* g_mask  = (const float*)d_in[1];
    const float* g_times = (const float*)d_in[2];
    const float* g_emb   = (const float*)d_in[3];
    const float* g_qW    = (const float*)d_in[4];
    const float* g_qb    = (const float*)d_in[5];
    const float* g_kW    = (const float*)d_in[6];
    const float* g_kb    = (const float*)d_in[7];
    const float* g_theta = (const float*)d_in[8];
    const float* g_mu    = (const float*)d_in[9];
    float* g_out = (float*)d_out;

    const int n_rows = in_sizes[2];               // B*LS = 16384
    const int smem_bytes = SMEM_FLOATS * sizeof(float);

    cudaFuncSetAttribute(concept_emb_kernel,
                         cudaFuncAttributeMaxDynamicSharedMemorySize, smem_bytes);

    const int blocks = (n_rows + RPC - 1) / RPC;  // 2048
    concept_emb_kernel<<<blocks, THREADS, smem_bytes>>>(
        g_ids, g_mask, g_times, g_emb, g_qW, g_qb, g_kW, g_kb,
        g_theta, g_mu, g_out, n_rows);
}

// round 8
// speedup vs baseline: 1.6134x; 1.6134x over previous
#include <cuda_runtime.h>

#define THREADS 128
#define RPC 8          // rows per CTA
#define WS 128         // Wt row stride (floats)
#define XS 132         // x / qk row stride (floats), mult of 4, not mult of 32

// shared memory layout (float offsets)
#define OFF_W   0
#define OFF_X   (128*WS)            // 16384
#define OFF_QK  (OFF_X + 32*XS)
#define OFF_B   (OFF_QK + 32*XS)
#define OFF_WR  (OFF_B + 128)
#define OFF_CWS (OFF_WR + 32)
#define OFF_CS  (OFF_CWS + 128)
#define SMEM_FLOATS (OFF_CS + 32)   // 25152 floats = 100608 B -> 2 CTAs/SM

// ---- packed fp32x2 helpers (sm_10x FFMA2 path, PTX-only) ----
__device__ __forceinline__ unsigned long long ffma2(unsigned long long a,
                                                    unsigned long long b,
                                                    unsigned long long c) {
    unsigned long long d;
    asm("fma.rn.f32x2 %0, %1, %2, %3;" : "=l"(d) : "l"(a), "l"(b), "l"(c));
    return d;
}
__device__ __forceinline__ unsigned long long dup2(float x) {
    unsigned long long r;
    asm("mov.b64 %0, {%1, %1};" : "=l"(r) : "f"(x));
    return r;
}
__device__ __forceinline__ void unpack2(unsigned long long v, float& lo, float& hi) {
    asm("mov.b64 {%0, %1}, %2;" : "=f"(lo), "=f"(hi) : "l"(v));
}

__global__ __launch_bounds__(THREADS, 2)
void concept_emb_kernel(const int*   __restrict__ g_ids,
                        const float* __restrict__ g_mask,
                        const float* __restrict__ g_times,
                        const float* __restrict__ g_emb,
                        const float* __restrict__ g_qW,
                        const float* __restrict__ g_qb,
                        const float* __restrict__ g_kW,
                        const float* __restrict__ g_kb,
                        const float* __restrict__ g_theta,
                        const float* __restrict__ g_mu,
                        float*       __restrict__ g_out,
                        int n_rows)
{
    extern __shared__ float sm[];
    float* Wt   = sm + OFF_W;    // [128 d][128] : Wt[d][j], j<64 = qW row j, j>=64 = kW row j-64
    float* xs   = sm + OFF_X;    // [32 n][132], plain layout
    float* qk   = sm + OFF_QK;   // [32 n][132] : cols 0..63 = q, 64..127 = k
    float* bs   = sm + OFF_B;    // [128] combined bias
    float* wrow = sm + OFF_WR;   // [32] sx * mask per concept
    float* cws  = sm + OFF_CWS;  // [4 warps][32]
    float* cs   = sm + OFF_CS;   // [32] attention column weights

    const int t    = threadIdx.x;
    const int lane = t & 31;
    const int wid  = t >> 5;

    // phase-2 mapping: warp owns j-quarter [32*wid, 32*wid+32), all 32 n.
    // lane = (ng, jg): ng = lane&3 -> INTERLEAVED rows {ng, ng+4, ..., ng+28};
    //                  jg = lane>>2 -> 4 consecutive j at jb.
    // x loads: 4 unique addrs (row stride 132 -> banks 4*ng) : conflict-free, bcast x8.
    // W loads: 8 unique addrs (banks 4*jg) : conflict-free 128B, bcast x4.
    const int ng = lane & 3;
    const int jg = lane >> 2;
    const int jb = 32 * wid + 4 * jg;

    // ---- stage [qW;kW] transposed into smem (once per CTA) ----
    {
        const float4* q4 = (const float4*)g_qW;
        const float4* k4 = (const float4*)g_kW;
        #pragma unroll
        for (int it = 0; it < 32; ++it) {
            int f  = it * 128 + t;       // float4 index in combined 4096
            int fl = f & 2047;
            float4 v = (f < 2048) ? q4[fl] : k4[fl];
            int j  = (fl >> 5) + ((f < 2048) ? 0 : 64);
            int d0 = (fl & 31) * 4;
            Wt[(d0+0)*WS + j] = v.x;
            Wt[(d0+1)*WS + j] = v.y;
            Wt[(d0+2)*WS + j] = v.z;
            Wt[(d0+3)*WS + j] = v.w;
        }
        bs[t] = (t < 64) ? g_qb[t] : g_kb[t - 64];
    }
    __syncthreads();

    // bias for this thread's 4-column j-tile, in a register across all rows
    const float4 bj = *(const float4*)&bs[jb];

    const int row0 = blockIdx.x * RPC;
    for (int rr = 0; rr < RPC; ++rr) {
        const int row = row0 + rr;
        const bool active = (row < n_rows);

        // ---- gather x[32][128] + per-concept pooling weights ----
        if (active) {
            const float4* emb4 = (const float4*)g_emb;
            #pragma unroll
            for (int r8 = 0; r8 < 8; ++r8) {
                int n = wid * 8 + r8;
                int id = g_ids[row * 32 + n];           // warp-uniform broadcast LDG
                float4 v = emb4[(long)id * 32 + lane];
                *(float4*)&xs[n * XS + lane * 4] = v;
            }
            if (t < 32) {
                int id = g_ids[row * 32 + t];
                float mk = g_mask[row * 32 + t];
                float tm = g_times[row];
                float z  = g_theta[id] - g_mu[id] * tm;
                float sx = 1.0f / (1.0f + __expf(-z));
                wrow[t] = sx * mk;
            }
        }
        __syncthreads();

        // ---- phase 2: [q|k] = x @ [qW;kW]^T ----
        // per-thread tile: 8 interleaved rows {ng+4r} x 4 j-cols at jb.
        if (active) {
            unsigned long long acc2[8][2];   // [r][jpair]: {jb,jb+1},{jb+2,jb+3}
            #pragma unroll
            for (int r = 0; r < 8; ++r) { acc2[r][0] = 0ULL; acc2[r][1] = 0ULL; }

            const float* xp = &xs[ng * XS];
            #pragma unroll 2
            for (int ds = 0; ds < 32; ++ds) {
                const int d = ds * 4;
                float4 xv[8];
                #pragma unroll
                for (int r = 0; r < 8; ++r)
                    xv[r] = *(const float4*)(xp + (4 * r) * XS + d);
                #pragma unroll
                for (int e = 0; e < 4; ++e) {
                    ulonglong2 wv = *(const ulonglong2*)(&Wt[(d + e) * WS + jb]);
                    #pragma unroll
                    for (int r = 0; r < 8; ++r) {
                        const float* xf = (const float*)&xv[r];
                        unsigned long long xd = dup2(xf[e]);
                        acc2[r][0] = ffma2(xd, wv.x, acc2[r][0]);
                        acc2[r][1] = ffma2(xd, wv.y, acc2[r][1]);
                    }
                }
            }
            #pragma unroll
            for (int r = 0; r < 8; ++r) {
                int n = ng + 4 * r;
                float v0, v1, v2, v3;
                unpack2(acc2[r][0], v0, v1);
                unpack2(acc2[r][1], v2, v3);
                float4 o = {v0 + bj.x, v1 + bj.y, v2 + bj.z, v3 + bj.w};
                *(float4*)&qk[n * XS + jb] = o;
            }
        }
        __syncthreads();

        // ---- phase 3: scores (column m = lane), softmax via shuffles,
        //      fold pooling weights into column vector c; packed f32x2 dot ----
        if (active) {
            unsigned long long s2[8];
            #pragma unroll
            for (int i = 0; i < 8; ++i) s2[i] = 0ULL;
            const float* kp = &qk[lane * XS + 64];     // k row m = lane
            const float* qp = &qk[(wid * 8) * XS];     // q rows 8w..8w+7 (broadcast)
            #pragma unroll 2
            for (int hs = 0; hs < 16; ++hs) {
                const int h = hs * 4;
                ulonglong2 kv = *(const ulonglong2*)(kp + h);
                #pragma unroll
                for (int i = 0; i < 8; ++i) {
                    ulonglong2 qv = *(const ulonglong2*)(qp + i * XS + h);
                    s2[i] = ffma2(qv.x, kv.x, s2[i]);
                    s2[i] = ffma2(qv.y, kv.y, s2[i]);
                }
            }
            float cpart = 0.f;
            #pragma unroll
            for (int i = 0; i < 8; ++i) {
                float a, b;
                unpack2(s2[i], a, b);
                float v = (a + b) * 0.125f;            // / sqrt(H=64)
                float mx = v;
                #pragma unroll
                for (int o = 16; o > 0; o >>= 1)
                    mx = fmaxf(mx, __shfl_xor_sync(0xffffffffu, mx, o));
                float ex = __expf(v - mx);
                float sum = ex;
                #pragma unroll
                for (int o = 16; o > 0; o >>= 1)
                    sum += __shfl_xor_sync(0xffffffffu, sum, o);
                cpart = fmaf(__fdividef(wrow[wid * 8 + i], sum), ex, cpart);
            }
            cws[wid * 32 + lane] = cpart;
        }
        __syncthreads();

        if (active && t < 32)
            cs[t] = cws[t] + cws[32 + t] + cws[64 + t] + cws[96 + t];
        __syncthreads();

        // ---- phase 4: pooled[d] = sum_m c[m] * x[m][d] ----
        if (active) {
            float o = 0.f;
            #pragma unroll
            for (int m = 0; m < 32; ++m)
                o = fmaf(cs[m], xs[m * XS + t], o);
            g_out[(long)row * 128 + t] = o;
        }
        // protect xs/wrow against next iteration's gather writes
        __syncthreads();
    }
}

extern "C" void kernel_launch(void* const* d_in, const int* in_sizes, int n_in,
                              void* d_out, int out_size)
{
    (void)n_in; (void)out_size;
    const int*   g_ids   = (const int*)  d_in[0];
    const float* g_mask  = (const float*)d_in[1];
    const float* g_times = (const float*)d_in[2];
    const float* g_emb   = (const float*)d_in[3];
    const float* g_qW    = (const float*)d_in[4];
    const float* g_qb    = (const float*)d_in[5];
    const float* g_kW    = (const float*)d_in[6];
    const float* g_kb    = (const float*)d_in[7];
    const float* g_theta = (const float*)d_in[8];
    const float* g_mu    = (const float*)d_in[9];
    float* g_out = (float*)d_out;

    const int n_rows = in_sizes[2];               // B*LS = 16384
    const int smem_bytes = SMEM_FLOATS * sizeof(float);

    cudaFuncSetAttribute(concept_emb_kernel,
                         cudaFuncAttributeMaxDynamicSharedMemorySize, smem_bytes);

    const int blocks = (n_rows + RPC - 1) / RPC;  // 2048
    concept_emb_kernel<<<blocks, THREADS, smem_bytes>>>(
        g_ids, g_mask, g_times, g_emb, g_qW, g_qb, g_kW, g_kb,
        g_theta, g_mu, g_out, n_rows);
}

// round 12
// speedup vs baseline: 1.6282x; 1.0092x over previous
#include <cuda_runtime.h>

#define THREADS 128
#define RPC 8          // rows per CTA
#define XS 132         // x / qk row stride (floats), mult of 4, not mult of 32

// shared memory layout (float offsets) — W no longer staged in smem
#define OFF_X   0
#define OFF_QK  (OFF_X + 32*XS)     // 4224
#define OFF_B   (OFF_QK + 32*XS)    // 8448
#define OFF_WR  (OFF_B + 128)
#define OFF_CWS (OFF_WR + 32)
#define OFF_CS  (OFF_CWS + 128)
#define SMEM_FLOATS (OFF_CS + 32)   // 8768 floats = 35072 B -> 4 CTAs/SM

// ---- packed fp32x2 helpers (sm_10x FFMA2 path, PTX-only) ----
__device__ __forceinline__ unsigned long long ffma2(unsigned long long a,
                                                    unsigned long long b,
                                                    unsigned long long c) {
    unsigned long long d;
    asm("fma.rn.f32x2 %0, %1, %2, %3;" : "=l"(d) : "l"(a), "l"(b), "l"(c));
    return d;
}
__device__ __forceinline__ void unpack2(unsigned long long v, float& lo, float& hi) {
    asm("mov.b64 {%0, %1}, %2;" : "=f"(lo), "=f"(hi) : "l"(v));
}

__global__ __launch_bounds__(THREADS, 4)
void concept_emb_kernel(const int*   __restrict__ g_ids,
                        const float* __restrict__ g_mask,
                        const float* __restrict__ g_times,
                        const float* __restrict__ g_emb,
                        const float* __restrict__ g_qW,
                        const float* __restrict__ g_qb,
                        const float* __restrict__ g_kW,
                        const float* __restrict__ g_kb,
                        const float* __restrict__ g_theta,
                        const float* __restrict__ g_mu,
                        float*       __restrict__ g_out,
                        int n_rows)
{
    extern __shared__ float sm[];
    float* xs   = sm + OFF_X;    // [32 n][132]
    float* qk   = sm + OFF_QK;   // [32 n][132] : cols 0..63 = q, 64..127 = k
    float* bs   = sm + OFF_B;    // [128] combined bias
    float* wrow = sm + OFF_WR;   // [32] sx * mask per concept
    float* cws  = sm + OFF_CWS;  // [4 warps][32]
    float* cs   = sm + OFF_CS;   // [32] attention column weights

    const int t    = threadIdx.x;
    const int lane = t & 31;
    const int wid  = t >> 5;

    // phase-2 mapping: warp owns j-quarter [32*wid, 32*wid+32), all 32 n.
    // ng = lane&3 -> interleaved rows {ng, ng+4, ..., ng+28}  (conflict-free LDS)
    // jg = lane>>2 -> 4 consecutive j at jb                    (8-way coalesced LDG)
    const int ng = lane & 3;
    const int jg = lane >> 2;
    const int jb = 32 * wid + 4 * jg;

    // W source rows: wid 0,1 -> qW rows jb; wid 2,3 -> kW rows jb-64.
    const float* Wsel = (wid < 2) ? g_qW : g_kW;
    const float* wbase = Wsel + (jb & 63) * 128;   // 4 consecutive rows of 128 floats

    if (t < 128) bs[t] = (t < 64) ? g_qb[t] : g_kb[t - 64];
    __syncthreads();

    // bias for this thread's 4-column j-tile
    const float4 bj = *(const float4*)&bs[jb];

    const int row0 = blockIdx.x * RPC;
    for (int rr = 0; rr < RPC; ++rr) {
        const int row = row0 + rr;
        const bool active = (row < n_rows);

        // ---- gather x[32][128] + per-concept pooling weights ----
        if (active) {
            const float4* emb4 = (const float4*)g_emb;
            #pragma unroll
            for (int r8 = 0; r8 < 8; ++r8) {
                int n = wid * 8 + r8;
                int id = g_ids[row * 32 + n];           // warp-uniform broadcast LDG
                float4 v = emb4[(long)id * 32 + lane];
                *(float4*)&xs[n * XS + lane * 4] = v;
            }
            if (t < 32) {
                int id = g_ids[row * 32 + t];
                float mk = g_mask[row * 32 + t];
                float tm = g_times[row];
                float z  = g_theta[id] - g_mu[id] * tm;
                float sx = 1.0f / (1.0f + __expf(-z));
                wrow[t] = sx * mk;
            }
        }
        __syncthreads();

        // ---- phase 2: [q|k] = x @ [qW;kW]^T ----
        // FFMA2 packed along d: acc[r][u] = {sum_even_d, sum_odd_d}.
        // x2 pairs come free from LDS.128; w2 pairs free from LDG.128 (L1-hit).
        if (active) {
            unsigned long long acc2[8][4];   // [r][u]: output (row ng+4r, col jb+u)
            #pragma unroll
            for (int r = 0; r < 8; ++r)
                #pragma unroll
                for (int u = 0; u < 4; ++u) acc2[r][u] = 0ULL;

            const float* xp = &xs[ng * XS];
            #pragma unroll 1
            for (int ds = 0; ds < 32; ++ds) {
                const int d = ds * 4;
                ulonglong2 wv[4];
                #pragma unroll
                for (int u = 0; u < 4; ++u)
                    wv[u] = *(const ulonglong2*)(wbase + u * 128 + d);
                #pragma unroll
                for (int rh = 0; rh < 2; ++rh) {
                    ulonglong2 xv[4];
                    #pragma unroll
                    for (int i = 0; i < 4; ++i)
                        xv[i] = *(const ulonglong2*)(xp + (4 * (rh * 4 + i)) * XS + d);
                    #pragma unroll
                    for (int i = 0; i < 4; ++i) {
                        const int r = rh * 4 + i;
                        #pragma unroll
                        for (int u = 0; u < 4; ++u) {
                            acc2[r][u] = ffma2(xv[i].x, wv[u].x, acc2[r][u]);
                            acc2[r][u] = ffma2(xv[i].y, wv[u].y, acc2[r][u]);
                        }
                    }
                }
            }
            #pragma unroll
            for (int r = 0; r < 8; ++r) {
                int n = ng + 4 * r;
                float4 o;
                float lo, hi;
                unpack2(acc2[r][0], lo, hi); o.x = lo + hi + bj.x;
                unpack2(acc2[r][1], lo, hi); o.y = lo + hi + bj.y;
                unpack2(acc2[r][2], lo, hi); o.z = lo + hi + bj.z;
                unpack2(acc2[r][3], lo, hi); o.w = lo + hi + bj.w;
                *(float4*)&qk[n * XS + jb] = o;
            }
        }
        __syncthreads();

        // ---- phase 3: scores (column m = lane), softmax via shuffles,
        //      fold pooling weights into column vector c; packed f32x2 dot ----
        if (active) {
            unsigned long long s2[8];
            #pragma unroll
            for (int i = 0; i < 8; ++i) s2[i] = 0ULL;
            const float* kp = &qk[lane * XS + 64];     // k row m = lane
            const float* qp = &qk[(wid * 8) * XS];     // q rows 8w..8w+7 (broadcast)
            #pragma unroll 2
            for (int hs = 0; hs < 16; ++hs) {
                const int h = hs * 4;
                ulonglong2 kv = *(const ulonglong2*)(kp + h);
                #pragma unroll
                for (int i = 0; i < 8; ++i) {
                    ulonglong2 qv = *(const ulonglong2*)(qp + i * XS + h);
                    s2[i] = ffma2(qv.x, kv.x, s2[i]);
                    s2[i] = ffma2(qv.y, kv.y, s2[i]);
                }
            }
            float cpart = 0.f;
            #pragma unroll
            for (int i = 0; i < 8; ++i) {
                float a, b;
                unpack2(s2[i], a, b);
                float v = (a + b) * 0.125f;            // / sqrt(H=64)
                float mx = v;
                #pragma unroll
                for (int o = 16; o > 0; o >>= 1)
                    mx = fmaxf(mx, __shfl_xor_sync(0xffffffffu, mx, o));
                float ex = __expf(v - mx);
                float sum = ex;
                #pragma unroll
                for (int o = 16; o > 0; o >>= 1)
                    sum += __shfl_xor_sync(0xffffffffu, sum, o);
                cpart = fmaf(__fdividef(wrow[wid * 8 + i], sum), ex, cpart);
            }
            cws[wid * 32 + lane] = cpart;
        }
        __syncthreads();

        if (active && t < 32)
            cs[t] = cws[t] + cws[32 + t] + cws[64 + t] + cws[96 + t];
        __syncthreads();

        // ---- phase 4: pooled[d] = sum_m c[m] * x[m][d] ----
        if (active) {
            float o = 0.f;
            #pragma unroll
            for (int m = 0; m < 32; ++m)
                o = fmaf(cs[m], xs[m * XS + t], o);
            g_out[(long)row * 128 + t] = o;
        }
        // protect xs/wrow against next iteration's gather writes
        __syncthreads();
    }
}

extern "C" void kernel_launch(void* const* d_in, const int* in_sizes, int n_in,
                              void* d_out, int out_size)
{
    (void)n_in; (void)out_size;
    const int*   g_ids   = (const int*)  d_in[0];
    const float* g_mask  = (const float*)d_in[1];
    const float* g_times = (const float*)d_in[2];
    const float* g_emb   = (const float*)d_in[3];
    const float* g_qW    = (const float*)d_in[4];
    const float* g_qb    = (const float*)d_in[5];
    const float* g_kW    = (const float*)d_in[6];
    const float* g_kb    = (const float*)d_in[7];
    const float* g_theta = (const float*)d_in[8];
    const float* g_mu    = (const float*)d_in[9];
    float* g_out = (float*)d_out;

    const int n_rows = in_sizes[2];               // B*LS = 16384
    const int smem_bytes = SMEM_FLOATS * sizeof(float);

    cudaFuncSetAttribute(concept_emb_kernel,
                         cudaFuncAttributeMaxDynamicSharedMemorySize, smem_bytes);

    const int blocks = (n_rows + RPC - 1) / RPC;  // 2048
    concept_emb_kernel<<<blocks, THREADS, smem_bytes>>>(
        g_ids, g_mask, g_times, g_emb, g_qW, g_qb, g_kW, g_kb,
        g_theta, g_mu, g_out, n_rows);
}